// round 14
// baseline (speedup 1.0000x reference)
#include <cuda_runtime.h>
#include <cuda_bf16.h>
#include <cstdint>
#include <math.h>

#define BATCH 4
#define CHAN  256
#define DIM   128
#define NTOK  4096
#define NCTA  148
#define NCHUNK (128 * 64)      // 128 tiles x 64 key-blocks

// ============================ scratch ============================
__device__ __nv_bfloat16 g_xt_hi[BATCH * NTOK * CHAN];
__device__ __nv_bfloat16 g_xt_lo[BATCH * NTOK * CHAN];
__device__ __nv_bfloat16 g_th_hi[BATCH * NTOK * DIM];
__device__ __nv_bfloat16 g_th_lo[BATCH * NTOK * DIM];
__device__ __nv_bfloat16 g_ph_hi[BATCH * NTOK * DIM];
__device__ __nv_bfloat16 g_ph_lo[BATCH * NTOK * DIM];
__device__ __nv_bfloat16 g_g_hi[BATCH * DIM * NTOK];
__device__ __nv_bfloat16 g_g_lo[BATCH * DIM * NTOK];
__device__ __nv_bfloat16 g_y_hi[BATCH * NTOK * DIM];
__device__ __nv_bfloat16 g_y_lo[BATCH * NTOK * DIM];
__device__ __nv_bfloat16 g_wt_hi[DIM * CHAN], g_wt_lo[DIM * CHAN];
__device__ __nv_bfloat16 g_wp_hi[DIM * CHAN], g_wp_lo[DIM * CHAN];
__device__ __nv_bfloat16 g_wg_hi[DIM * CHAN], g_wg_lo[DIM * CHAN];
__device__ __nv_bfloat16 g_ww_hi[CHAN * DIM], g_ww_lo[CHAN * DIM];
__device__ float g_wy[BATCH * CHAN * NTOK];
__device__ float g_ps1[BATCH * 32 * CHAN];
__device__ float g_ps2[BATCH * 32 * CHAN];
__device__ float g_mean[CHAN];
__device__ float g_istd[CHAN];
__device__ float g_py [128 * 3 * 128 * 128];   // partial y   [tile][slot][r][c]
__device__ float g_prs[128 * 3 * 128];         // partial rowsum

// ============================ helpers ============================
__device__ __forceinline__ uint32_t smem_to_u32(const void* p) {
    uint32_t a;
    asm("{ .reg .u64 t; cvta.to.shared.u64 t, %1; cvt.u32.u64 %0, t; }" : "=r"(a) : "l"(p));
    return a;
}
__device__ __forceinline__ void cpa16(uint32_t saddr, const void* g) {
    asm volatile("cp.async.cg.shared.global [%0], [%1], 16;" :: "r"(saddr), "l"(g));
}
__device__ __forceinline__ void cpa_commit() {
    asm volatile("cp.async.commit_group;" ::: "memory");
}
__device__ __forceinline__ void cpa_wait1() {
    asm volatile("cp.async.wait_group 1;" ::: "memory");
}
__device__ __forceinline__ void ldsm_x4(uint32_t* r, uint32_t addr) {
    asm volatile("ldmatrix.sync.aligned.m8n8.x4.shared.b16 {%0,%1,%2,%3}, [%4];"
                 : "=r"(r[0]), "=r"(r[1]), "=r"(r[2]), "=r"(r[3]) : "r"(addr));
}
__device__ __forceinline__ void mma_bf16(float* c, const uint32_t* a, const uint32_t* b) {
    asm volatile("mma.sync.aligned.m16n8k16.row.col.f32.bf16.bf16.f32 "
                 "{%0,%1,%2,%3}, {%4,%5,%6,%7}, {%8,%9}, {%0,%1,%2,%3};"
                 : "+f"(c[0]), "+f"(c[1]), "+f"(c[2]), "+f"(c[3])
                 : "r"(a[0]), "r"(a[1]), "r"(a[2]), "r"(a[3]), "r"(b[0]), "r"(b[1]));
}
__device__ __forceinline__ void split_write2(__nv_bfloat16* hi, __nv_bfloat16* lo,
                                             float a, float b) {
    __nv_bfloat16 h0 = __float2bfloat16_rn(a), h1 = __float2bfloat16_rn(b);
    __nv_bfloat16 l0 = __float2bfloat16_rn(a - __bfloat162float(h0));
    __nv_bfloat16 l1 = __float2bfloat16_rn(b - __bfloat162float(h1));
    *(__nv_bfloat162*)hi = __nv_bfloat162(h0, h1);
    *(__nv_bfloat162*)lo = __nv_bfloat162(l0, l1);
}
__device__ __forceinline__ uint32_t pack_split(float a, float b, uint32_t& lo_out) {
    __nv_bfloat16 ha = __float2bfloat16_rn(a), hb = __float2bfloat16_rn(b);
    __nv_bfloat16 la = __float2bfloat16_rn(a - __bfloat162float(ha));
    __nv_bfloat16 lb = __float2bfloat16_rn(b - __bfloat162float(hb));
    __nv_bfloat162 h(ha, hb), l(la, lb);
    lo_out = *(uint32_t*)&l;
    return *(uint32_t*)&h;
}

// ============================ merged input split (x transpose + weights) ============================
// blocks [0, 4096): x transpose/split; blocks [4096, 4224): weight split
__global__ __launch_bounds__(256)
void split_inputs(const float* __restrict__ x,
                  const float* __restrict__ wt, const float* __restrict__ wp,
                  const float* __restrict__ wg, const float* __restrict__ ww,
                  __nv_bfloat16* __restrict__ xh, __nv_bfloat16* __restrict__ xl,
                  __nv_bfloat16* __restrict__ wth, __nv_bfloat16* __restrict__ wtl,
                  __nv_bfloat16* __restrict__ wph, __nv_bfloat16* __restrict__ wpl,
                  __nv_bfloat16* __restrict__ wgh, __nv_bfloat16* __restrict__ wgl,
                  __nv_bfloat16* __restrict__ wwh, __nv_bfloat16* __restrict__ wwl)
{
    const int bid = blockIdx.x;
    if (bid < 4096) {
        __shared__ float tile[32][33];
        const int b = bid >> 10, c0 = ((bid >> 7) & 7) * 32, n0 = (bid & 127) * 32;
        const int tr = threadIdx.x >> 5, tc = threadIdx.x & 31;
        const float* src = x + ((size_t)b * CHAN + c0) * NTOK + n0;
        #pragma unroll
        for (int i = 0; i < 4; i++)
            tile[tr + 8 * i][tc] = src[(size_t)(tr + 8 * i) * NTOK + tc];
        __syncthreads();
        __nv_bfloat16* ph = xh + ((size_t)b * NTOK + n0) * CHAN + c0;
        __nv_bfloat16* pl = xl + ((size_t)b * NTOK + n0) * CHAN + c0;
        #pragma unroll
        for (int i = 0; i < 4; i++) {
            int rn = tr + 8 * i;
            float v = tile[tc][rn];
            __nv_bfloat16 h = __float2bfloat16_rn(v);
            ph[(size_t)rn * CHAN + tc] = h;
            pl[(size_t)rn * CHAN + tc] = __float2bfloat16_rn(v - __bfloat162float(h));
        }
    } else {
        int idx = (bid - 4096) * 256 + threadIdx.x;    // 0..32767
        const float* srcs[4] = {wt, wp, wg, ww};
        __nv_bfloat16* his[4] = {wth, wph, wgh, wwh};
        __nv_bfloat16* los[4] = {wtl, wpl, wgl, wwl};
        #pragma unroll
        for (int s = 0; s < 4; s++) {
            float v = srcs[s][idx];
            __nv_bfloat16 h = __float2bfloat16_rn(v);
            his[s][idx] = h;
            los[s][idx] = __float2bfloat16_rn(v - __bfloat162float(h));
        }
    }
}

// ============================ persistent merged projection GEMM ============================
// linear tile t in [0, 384): role = t>>7 (0=theta,1=phi,2=g), b = (t&127)>>5, by = t&31
#define SMEM_TT (2 * (2 * 128 * 80 + 2 * 128 * 80))   // 81920

__global__ __launch_bounds__(256, 2)
void proj3(const __nv_bfloat16* __restrict__ xth, const __nv_bfloat16* __restrict__ xtl,
           const __nv_bfloat16* __restrict__ wth, const __nv_bfloat16* __restrict__ wtl,
           const __nv_bfloat16* __restrict__ wph, const __nv_bfloat16* __restrict__ wpl,
           const __nv_bfloat16* __restrict__ wgh, const __nv_bfloat16* __restrict__ wgl,
           __nv_bfloat16* __restrict__ thh, __nv_bfloat16* __restrict__ thl,
           __nv_bfloat16* __restrict__ phh, __nv_bfloat16* __restrict__ phl,
           __nv_bfloat16* __restrict__ ghh, __nv_bfloat16* __restrict__ ghl,
           const float* __restrict__ tb, const float* __restrict__ pb,
           const float* __restrict__ gb)
{
    constexpr int A_BYTES = 128 * 80;
    constexpr int B_BYTES = 128 * 80;
    constexpr int SS = 2 * A_BYTES + 2 * B_BYTES;

    extern __shared__ char smem[];
    const uint32_t sb = smem_to_u32(smem);

    const int tid = threadIdx.x;
    const int lane = tid & 31, wid = tid >> 5;
    const int wr = wid >> 2, wc = wid & 3;

    const int a_rl = ((lane >> 3) & 1) * 8 + (lane & 7);
    const int a_cl = lane >> 4;
    const int b_rl = (lane >> 4) * 8 + (lane & 7);
    const int b_cl = (lane >> 3) & 1;

    for (int t4 = blockIdx.x; t4 < 384; t4 += NCTA) {
        const int role = t4 >> 7;
        const int b = (t4 & 127) >> 5;
        const int by = t4 & 31;
        const size_t xoff = (size_t)b * NTOK * CHAN + (size_t)by * 128 * CHAN;

        const __nv_bfloat16 *pAh, *pAl, *pBh, *pBl;
        if (role == 0)      { pAh = xth + xoff; pAl = xtl + xoff; pBh = wth; pBl = wtl; }
        else if (role == 1) { pAh = xth + xoff; pAl = xtl + xoff; pBh = wph; pBl = wpl; }
        else                { pAh = wgh;        pAl = wgl;        pBh = xth + xoff; pBl = xtl + xoff; }

        float acc[4][4][4] = {};

        auto load_stage = [&](int s, int kc) {
            const uint32_t st = sb + s * SS;
            const int k0 = kc * 32;
            #pragma unroll
            for (int i = tid; i < 512; i += 256) {
                int r = i >> 2, c = i & 3;
                uint32_t so = st + r * 80 + c * 16;
                size_t g = (size_t)r * CHAN + k0 + c * 8;
                cpa16(so,           pAh + g);
                cpa16(so + A_BYTES, pAl + g);
            }
            #pragma unroll
            for (int i = tid; i < 512; i += 256) {
                int r = i >> 2, c = i & 3;
                uint32_t so = st + 2 * A_BYTES + r * 80 + c * 16;
                size_t g = (size_t)r * CHAN + k0 + c * 8;
                cpa16(so,           pBh + g);
                cpa16(so + B_BYTES, pBl + g);
            }
        };

        load_stage(0, 0); cpa_commit();
        load_stage(1, 1); cpa_commit();

        for (int kc = 0; kc < 8; kc++) {
            cpa_wait1();
            __syncthreads();
            const uint32_t st = sb + (kc & 1) * SS;
            const uint32_t uAh = st, uAl = st + A_BYTES;
            const uint32_t uBh = st + 2 * A_BYTES, uBl = uBh + B_BYTES;

            #pragma unroll
            for (int ks = 0; ks < 2; ks++) {
                const int kk8 = ks * 2;
                uint32_t bh[4][2], bl[4][2];
                #pragma unroll
                for (int j2 = 0; j2 < 2; j2++) {
                    int nrow = wc * 32 + j2 * 16 + b_rl;
                    uint32_t off = (uint32_t)(nrow * 80 + (kk8 + b_cl) * 16);
                    uint32_t r[4];
                    ldsm_x4(r, uBh + off);
                    bh[j2 * 2 + 0][0] = r[0]; bh[j2 * 2 + 0][1] = r[1];
                    bh[j2 * 2 + 1][0] = r[2]; bh[j2 * 2 + 1][1] = r[3];
                    ldsm_x4(r, uBl + off);
                    bl[j2 * 2 + 0][0] = r[0]; bl[j2 * 2 + 0][1] = r[1];
                    bl[j2 * 2 + 1][0] = r[2]; bl[j2 * 2 + 1][1] = r[3];
                }
                #pragma unroll
                for (int t = 0; t < 4; t++) {
                    int mrow = wr * 64 + t * 16 + a_rl;
                    uint32_t off = (uint32_t)(mrow * 80 + (kk8 + a_cl) * 16);
                    uint32_t ah[4], al[4];
                    ldsm_x4(ah, uAh + off);
                    ldsm_x4(al, uAl + off);
                    #pragma unroll
                    for (int j = 0; j < 4; j++) mma_bf16(acc[t][j], ah, bh[j]);
                    #pragma unroll
                    for (int j = 0; j < 4; j++) mma_bf16(acc[t][j], ah, bl[j]);
                    #pragma unroll
                    for (int j = 0; j < 4; j++) mma_bf16(acc[t][j], al, bh[j]);
                }
            }
            __syncthreads();
            int nk = kc + 2;
            if (nk < 8) load_stage(kc & 1, nk);
            cpa_commit();
        }

        if (role < 2) {
            const float* bias = role ? pb : tb;
            __nv_bfloat16* oh = (role ? phh : thh) + (size_t)b * NTOK * DIM;
            __nv_bfloat16* ol = (role ? phl : thl) + (size_t)b * NTOK * DIM;
            #pragma unroll
            for (int t = 0; t < 4; t++) {
                int row = by * 128 + wr * 64 + t * 16 + (lane >> 2);
                #pragma unroll
                for (int j = 0; j < 4; j++) {
                    int col = wc * 32 + j * 8 + ((lane & 3) << 1);
                    float c0 = bias[col], c1 = bias[col + 1];
                    split_write2(oh + (size_t)row * DIM + col, ol + (size_t)row * DIM + col,
                                 acc[t][j][0] + c0, acc[t][j][1] + c1);
                    split_write2(oh + (size_t)(row + 8) * DIM + col, ol + (size_t)(row + 8) * DIM + col,
                                 acc[t][j][2] + c0, acc[t][j][3] + c1);
                }
            }
        } else {
            __nv_bfloat16* oh = ghh + (size_t)b * DIM * NTOK;
            __nv_bfloat16* ol = ghl + (size_t)b * DIM * NTOK;
            #pragma unroll
            for (int t = 0; t < 4; t++) {
                int row = wr * 64 + t * 16 + (lane >> 2);
                float r0 = gb[row], r1 = gb[row + 8];
                #pragma unroll
                for (int j = 0; j < 4; j++) {
                    int col = by * 128 + wc * 32 + j * 8 + ((lane & 3) << 1);
                    split_write2(oh + (size_t)row * NTOK + col, ol + (size_t)row * NTOK + col,
                                 acc[t][j][0] + r0, acc[t][j][1] + r0);
                    split_write2(oh + (size_t)(row + 8) * NTOK + col, ol + (size_t)(row + 8) * NTOK + col,
                                 acc[t][j][2] + r1, acc[t][j][3] + r1);
                }
            }
        }
    }
}

// ============================ wy GEMM + BN partial stats ============================
#define SMEM_WY (SMEM_TT + 4096)

__global__ __launch_bounds__(256, 2)
void mma_wy(const __nv_bfloat16* __restrict__ Ah, const __nv_bfloat16* __restrict__ Al,
            const __nv_bfloat16* __restrict__ Bh, const __nv_bfloat16* __restrict__ Bl,
            float* __restrict__ C, const float* __restrict__ bias,
            float* __restrict__ ps1, float* __restrict__ ps2)
{
    constexpr int A_BYTES = 128 * 80;
    constexpr int B_BYTES = 128 * 80;
    constexpr int SS = 2 * A_BYTES + 2 * B_BYTES;

    extern __shared__ char smem[];
    const uint32_t sb = smem_to_u32(smem);
    float* sred = (float*)(smem + 2 * SS);

    const int tid = threadIdx.x;
    const int lane = tid & 31, wid = tid >> 5;
    const int wr = wid >> 2, wc = wid & 3;
    const int b  = blockIdx.z;
    const int m0 = blockIdx.y * 128;
    const int n0 = blockIdx.x * 128;

    const __nv_bfloat16* pAh = Ah + (size_t)m0 * DIM;
    const __nv_bfloat16* pAl = Al + (size_t)m0 * DIM;
    const __nv_bfloat16* pBh = Bh + (size_t)b * NTOK * DIM + (size_t)n0 * DIM;
    const __nv_bfloat16* pBl = Bl + (size_t)b * NTOK * DIM + (size_t)n0 * DIM;

    float acc[4][4][4] = {};

    const int a_rl = ((lane >> 3) & 1) * 8 + (lane & 7);
    const int a_cl = lane >> 4;
    const int b_rl = (lane >> 4) * 8 + (lane & 7);
    const int b_cl = (lane >> 3) & 1;

    auto load_stage = [&](int s, int kc) {
        const uint32_t st = sb + s * SS;
        const int k0 = kc * 32;
        #pragma unroll
        for (int i = tid; i < 512; i += 256) {
            int r = i >> 2, c = i & 3;
            uint32_t so = st + r * 80 + c * 16;
            size_t g = (size_t)r * DIM + k0 + c * 8;
            cpa16(so,           pAh + g);
            cpa16(so + A_BYTES, pAl + g);
        }
        #pragma unroll
        for (int i = tid; i < 512; i += 256) {
            int r = i >> 2, c = i & 3;
            uint32_t so = st + 2 * A_BYTES + r * 80 + c * 16;
            size_t g = (size_t)r * DIM + k0 + c * 8;
            cpa16(so,           pBh + g);
            cpa16(so + B_BYTES, pBl + g);
        }
    };

    load_stage(0, 0); cpa_commit();
    load_stage(1, 1); cpa_commit();

    for (int kc = 0; kc < 4; kc++) {
        cpa_wait1();
        __syncthreads();
        const uint32_t st = sb + (kc & 1) * SS;
        const uint32_t uAh = st, uAl = st + A_BYTES;
        const uint32_t uBh = st + 2 * A_BYTES, uBl = uBh + B_BYTES;

        #pragma unroll
        for (int ks = 0; ks < 2; ks++) {
            const int kk8 = ks * 2;
            uint32_t bh[4][2], bl[4][2];
            #pragma unroll
            for (int j2 = 0; j2 < 2; j2++) {
                int nrow = wc * 32 + j2 * 16 + b_rl;
                uint32_t off = (uint32_t)(nrow * 80 + (kk8 + b_cl) * 16);
                uint32_t r[4];
                ldsm_x4(r, uBh + off);
                bh[j2 * 2 + 0][0] = r[0]; bh[j2 * 2 + 0][1] = r[1];
                bh[j2 * 2 + 1][0] = r[2]; bh[j2 * 2 + 1][1] = r[3];
                ldsm_x4(r, uBl + off);
                bl[j2 * 2 + 0][0] = r[0]; bl[j2 * 2 + 0][1] = r[1];
                bl[j2 * 2 + 1][0] = r[2]; bl[j2 * 2 + 1][1] = r[3];
            }
            #pragma unroll
            for (int t = 0; t < 4; t++) {
                int mrow = wr * 64 + t * 16 + a_rl;
                uint32_t off = (uint32_t)(mrow * 80 + (kk8 + a_cl) * 16);
                uint32_t ah[4], al[4];
                ldsm_x4(ah, uAh + off);
                ldsm_x4(al, uAl + off);
                #pragma unroll
                for (int j = 0; j < 4; j++) mma_bf16(acc[t][j], ah, bh[j]);
                #pragma unroll
                for (int j = 0; j < 4; j++) mma_bf16(acc[t][j], ah, bl[j]);
                #pragma unroll
                for (int j = 0; j < 4; j++) mma_bf16(acc[t][j], al, bh[j]);
            }
        }
        __syncthreads();
        int nk = kc + 2;
        if (nk < 4) load_stage(kc & 1, nk);
        cpa_commit();
    }

    float s1[8] = {}, s2[8] = {};
    float* Cp = C + (size_t)b * CHAN * NTOK;
    #pragma unroll
    for (int t = 0; t < 4; t++) {
        int row = m0 + wr * 64 + t * 16 + (lane >> 2);
        float b0 = bias[row], b1 = bias[row + 8];
        #pragma unroll
        for (int j = 0; j < 4; j++) {
            int col = n0 + wc * 32 + j * 8 + ((lane & 3) << 1);
            float v0 = acc[t][j][0] + b0, v1 = acc[t][j][1] + b0;
            float v2 = acc[t][j][2] + b1, v3 = acc[t][j][3] + b1;
            *(float2*)(Cp + (size_t)row * NTOK + col)       = make_float2(v0, v1);
            *(float2*)(Cp + (size_t)(row + 8) * NTOK + col) = make_float2(v2, v3);
            s1[t * 2 + 0] += v0 + v1;  s2[t * 2 + 0] += v0 * v0 + v1 * v1;
            s1[t * 2 + 1] += v2 + v3;  s2[t * 2 + 1] += v2 * v2 + v3 * v3;
        }
    }
    #pragma unroll
    for (int i = 0; i < 8; i++) {
        s1[i] += __shfl_xor_sync(0xffffffffu, s1[i], 1);
        s1[i] += __shfl_xor_sync(0xffffffffu, s1[i], 2);
        s2[i] += __shfl_xor_sync(0xffffffffu, s2[i], 1);
        s2[i] += __shfl_xor_sync(0xffffffffu, s2[i], 2);
    }
    __syncthreads();
    if ((lane & 3) == 0) {
        #pragma unroll
        for (int i = 0; i < 8; i++) {
            int rl = (i >> 1) * 16 + (lane >> 2) + (i & 1) * 8;
            sred[(wr * 4 + wc) * 64 + rl] = s1[i];
            sred[512 + (wr * 4 + wc) * 64 + rl] = s2[i];
        }
    }
    __syncthreads();
    if (tid < 128) {
        int wrx = tid >> 6, rl = tid & 63;
        float a1 = 0.0f, a2 = 0.0f;
        #pragma unroll
        for (int w = 0; w < 4; w++) {
            a1 += sred[(wrx * 4 + w) * 64 + rl];
            a2 += sred[512 + (wrx * 4 + w) * 64 + rl];
        }
        int c = m0 + wrx * 64 + rl;
        size_t pidx = ((size_t)b * 32 + blockIdx.x) * CHAN + c;
        ps1[pidx] = a1;
        ps2[pidx] = a2;
    }
}

// ============================ BN reduce ============================
__global__ __launch_bounds__(128)
void bn_reduce(const float* __restrict__ ps1, const float* __restrict__ ps2)
{
    const int c = blockIdx.x;
    const int t = threadIdx.x;
    float s1 = ps1[(size_t)t * CHAN + c];
    float s2 = ps2[(size_t)t * CHAN + c];
    #pragma unroll
    for (int o = 16; o; o >>= 1) {
        s1 += __shfl_xor_sync(0xffffffffu, s1, o);
        s2 += __shfl_xor_sync(0xffffffffu, s2, o);
    }
    __shared__ float r1[4], r2[4];
    if ((t & 31) == 0) { r1[t >> 5] = s1; r2[t >> 5] = s2; }
    __syncthreads();
    if (t == 0) {
        s1 = (r1[0] + r1[1]) + (r1[2] + r1[3]);
        s2 = (r2[0] + r2[1]) + (r2[2] + r2[3]);
        float mean = s1 * (1.0f / 16384.0f);
        float var  = s2 * (1.0f / 16384.0f) - mean * mean;
        g_mean[c] = mean;
        g_istd[c] = rsqrtf(var + 1e-5f);
    }
}

// ============================ BN apply + residual ============================
__global__ __launch_bounds__(256)
void bn_apply(const float* __restrict__ wy, const float* __restrict__ x,
              const float* __restrict__ gamma, const float* __restrict__ beta,
              float* __restrict__ out)
{
    int i4 = blockIdx.x * 256 + threadIdx.x;
    int c = (i4 >> 10) & (CHAN - 1);
    float is = g_istd[c];
    float ga = gamma[c] * is;
    float be = beta[c] - g_mean[c] * ga;
    float4 w = ((const float4*)wy)[i4];
    float4 xx = ((const float4*)x)[i4];
    float4 o;
    o.x = w.x * ga + be + xx.x;
    o.y = w.y * ga + be + xx.y;
    o.z = w.z * ga + be + xx.z;
    o.w = w.w * ga + be + xx.w;
    ((float4*)out)[i4] = o;
}

// ============================ persistent fused attention (split-K) ============================
#define TH_STR   272
#define PHI_STR  272
#define G_STR    144
#define TH_HALF  (128 * TH_STR)
#define TH_BYTES (2 * TH_HALF)
#define PHI_HALF (64 * PHI_STR)
#define PHI_STAGE (2 * PHI_HALF)
#define G_HALF   (128 * G_STR)
#define G_STAGE  (2 * G_HALF)
#define PHI_OFF  TH_BYTES
#define G_OFF    (PHI_OFF + 2 * PHI_STAGE)
#define FUSED_SMEM (G_OFF + 2 * G_STAGE)

__global__ __launch_bounds__(256, 1)
void fused_attn(const __nv_bfloat16* __restrict__ thh, const __nv_bfloat16* __restrict__ thl,
                const __nv_bfloat16* __restrict__ phh, const __nv_bfloat16* __restrict__ phl,
                const __nv_bfloat16* __restrict__ ghh, const __nv_bfloat16* __restrict__ ghl,
                float* __restrict__ py, float* __restrict__ prs)
{
    extern __shared__ char smem[];
    const uint32_t sb = smem_to_u32(smem);
    const int tid = threadIdx.x;
    const int lane = tid & 31, wid = tid >> 5;
    const int k = blockIdx.x;

    const int c0 = (NCHUNK * k) / NCTA;
    const int c1 = (NCHUNK * (k + 1)) / NCTA;

    const int a_rl = ((lane >> 3) & 1) * 8 + (lane & 7);
    const int a_cl = lane >> 4;
    const int b_rl = (lane >> 4) * 8 + (lane & 7);
    const int b_cl = (lane >> 3) & 1;

    int cpos = c0;
    while (cpos < c1) {
        const int tile = cpos >> 6;
        const int tstart = tile << 6;
        const int it0 = cpos - tstart;
        const int it1 = min(c1 - tstart, 64);
        const int b = tile >> 5;
        const int m0 = (tile & 31) * 128;
        const int kfirst = (NCTA * (tstart + 1) - 1) / NCHUNK;
        const int slot = k - kfirst;

        const __nv_bfloat16* pth = thh + ((size_t)b * NTOK + m0) * DIM;
        const __nv_bfloat16* ptl = thl + ((size_t)b * NTOK + m0) * DIM;
        const __nv_bfloat16* pph = phh + (size_t)b * NTOK * DIM;
        const __nv_bfloat16* ppl = phl + (size_t)b * NTOK * DIM;
        const __nv_bfloat16* pgh = ghh + (size_t)b * DIM * NTOK;
        const __nv_bfloat16* pgl = ghl + (size_t)b * DIM * NTOK;

        __syncthreads();   // protect smem reuse across segments

        // theta tile
        #pragma unroll
        for (int i = tid; i < 4096; i += 256) {
            int h = i >> 11, rem = i & 2047;
            int r = rem >> 4, c = rem & 15;
            const __nv_bfloat16* src = h ? ptl : pth;
            cpa16(sb + h * TH_HALF + r * TH_STR + c * 16, src + (size_t)r * DIM + c * 8);
        }

        auto load_stage = [&](int s, int nt) {
            uint32_t pb = sb + PHI_OFF + s * PHI_STAGE;
            const __nv_bfloat16* sph = pph + (size_t)(nt * 64) * DIM;
            const __nv_bfloat16* spl = ppl + (size_t)(nt * 64) * DIM;
            #pragma unroll
            for (int i = tid; i < 2048; i += 256) {
                int h = i >> 10, rem = i & 1023;
                int r = rem >> 4, c = rem & 15;
                const __nv_bfloat16* src = h ? spl : sph;
                cpa16(pb + h * PHI_HALF + r * PHI_STR + c * 16, src + (size_t)r * DIM + c * 8);
            }
            uint32_t gbuf = sb + G_OFF + s * G_STAGE;
            const __nv_bfloat16* sgh = pgh + nt * 64;
            const __nv_bfloat16* sgl = pgl + nt * 64;
            #pragma unroll
            for (int i = tid; i < 2048; i += 256) {
                int h = i >> 10, rem = i & 1023;
                int r = rem >> 3, c = rem & 7;
                const __nv_bfloat16* src = h ? sgl : sgh;
                cpa16(gbuf + h * G_HALF + r * G_STR + c * 16, src + (size_t)r * NTOK + c * 8);
            }
        };

        load_stage(it0 & 1, it0);
        cpa_commit();
        if (it0 + 1 < it1) load_stage((it0 + 1) & 1, it0 + 1);
        cpa_commit();

        float yacc[16][4] = {};
        float rs0 = 0.0f, rs1 = 0.0f;
        const uint32_t a_base = sb + (uint32_t)(16 * wid + a_rl) * TH_STR + a_cl * 16;

        for (int nt = it0; nt < it1; nt++) {
            cpa_wait1();
            __syncthreads();
            const uint32_t uph = sb + PHI_OFF + (nt & 1) * PHI_STAGE;
            const uint32_t ug  = sb + G_OFF + (nt & 1) * G_STAGE;

            float S[8][4] = {};
            #pragma unroll
            for (int ks = 0; ks < 8; ks++) {
                uint32_t ath[4], atl[4];
                uint32_t aoff = a_base + ks * 32;
                ldsm_x4(ath, aoff);
                ldsm_x4(atl, aoff + TH_HALF);
                uint32_t bh[8][2], bl[8][2];
                #pragma unroll
                for (int f = 0; f < 4; f++) {
                    uint32_t boff = (uint32_t)(16 * f + b_rl) * PHI_STR + (2 * ks + b_cl) * 16;
                    uint32_t r[4];
                    ldsm_x4(r, uph + boff);
                    bh[2 * f][0] = r[0]; bh[2 * f][1] = r[1];
                    bh[2 * f + 1][0] = r[2]; bh[2 * f + 1][1] = r[3];
                    ldsm_x4(r, uph + PHI_HALF + boff);
                    bl[2 * f][0] = r[0]; bl[2 * f][1] = r[1];
                    bl[2 * f + 1][0] = r[2]; bl[2 * f + 1][1] = r[3];
                }
                #pragma unroll
                for (int j = 0; j < 8; j++) mma_bf16(S[j], ath, bh[j]);
                #pragma unroll
                for (int j = 0; j < 8; j++) mma_bf16(S[j], ath, bl[j]);
                #pragma unroll
                for (int j = 0; j < 8; j++) mma_bf16(S[j], atl, bh[j]);
            }

            #pragma unroll
            for (int ks2 = 0; ks2 < 4; ks2++) {
                uint32_t gh[16][2], gl[16][2];
                #pragma unroll
                for (int dd = 0; dd < 8; dd++) {
                    uint32_t boff = (uint32_t)(16 * dd + b_rl) * G_STR + (2 * ks2 + b_cl) * 16;
                    uint32_t r[4];
                    ldsm_x4(r, ug + boff);
                    gh[2 * dd][0] = r[0]; gh[2 * dd][1] = r[1];
                    gh[2 * dd + 1][0] = r[2]; gh[2 * dd + 1][1] = r[3];
                    ldsm_x4(r, ug + G_HALF + boff);
                    gl[2 * dd][0] = r[0]; gl[2 * dd][1] = r[1];
                    gl[2 * dd + 1][0] = r[2]; gl[2 * dd + 1][1] = r[3];
                }
                float e0 = __expf(S[2 * ks2][0]),     e1 = __expf(S[2 * ks2][1]);
                float e2 = __expf(S[2 * ks2][2]),     e3 = __expf(S[2 * ks2][3]);
                float e4 = __expf(S[2 * ks2 + 1][0]), e5 = __expf(S[2 * ks2 + 1][1]);
                float e6 = __expf(S[2 * ks2 + 1][2]), e7 = __expf(S[2 * ks2 + 1][3]);
                rs0 += (e0 + e1) + (e4 + e5);
                rs1 += (e2 + e3) + (e6 + e7);
                uint32_t Ph[4], Pl[4];
                Ph[0] = pack_split(e0, e1, Pl[0]);
                Ph[1] = pack_split(e2, e3, Pl[1]);
                Ph[2] = pack_split(e4, e5, Pl[2]);
                Ph[3] = pack_split(e6, e7, Pl[3]);
                #pragma unroll
                for (int j = 0; j < 16; j++) mma_bf16(yacc[j], Ph, gh[j]);
                #pragma unroll
                for (int j = 0; j < 16; j++) mma_bf16(yacc[j], Ph, gl[j]);
                #pragma unroll
                for (int j = 0; j < 16; j++) mma_bf16(yacc[j], Pl, gh[j]);
            }

            __syncthreads();
            if (nt + 2 < it1) load_stage(nt & 1, nt + 2);
            cpa_commit();
        }

        // ---- segment epilogue: partial rowsums + partial fp32 y ----
        rs0 += __shfl_xor_sync(0xffffffffu, rs0, 1);
        rs0 += __shfl_xor_sync(0xffffffffu, rs0, 2);
        rs1 += __shfl_xor_sync(0xffffffffu, rs1, 1);
        rs1 += __shfl_xor_sync(0xffffffffu, rs1, 2);

        float* pys = py + ((size_t)(tile * 3 + slot)) * (128 * 128);
        float* prss = prs + (tile * 3 + slot) * 128;
        int row = 16 * wid + (lane >> 2);
        if ((lane & 3) == 0) { prss[row] = rs0; prss[row + 8] = rs1; }
        #pragma unroll
        for (int j = 0; j < 16; j++) {
            int col = 8 * j + 2 * (lane & 3);
            *(float2*)(pys + (size_t)row * 128 + col)       = make_float2(yacc[j][0], yacc[j][1]);
            *(float2*)(pys + (size_t)(row + 8) * 128 + col) = make_float2(yacc[j][2], yacc[j][3]);
        }

        cpos = tstart + it1;
    }
}

// ============================ combine partials -> normalized split y (coalesced) ============================
__global__ __launch_bounds__(256)
void combine_y(const float* __restrict__ py, const float* __restrict__ prs,
               __nv_bfloat16* __restrict__ y_hi, __nv_bfloat16* __restrict__ y_lo)
{
    const int tile = blockIdx.x;
    const int b = tile >> 5;
    const int m0 = (tile & 31) * 128;
    const int kfirst = (NCTA * (tile * 64 + 1) - 1) / NCHUNK;
    const int klast  = (NCTA * (tile * 64 + 64) - 1) / NCHUNK;
    const int ns = klast - kfirst + 1;

    const int t = threadIdx.x;
    __shared__ float sinv[128];
    if (t < 128) {
        float rs = 0.0f;
        for (int s = 0; s < ns; s++) rs += prs[(tile * 3 + s) * 128 + t];
        sinv[t] = 1.0f / rs;
    }
    __syncthreads();

    const float* base = py + ((size_t)tile * 3) * (128 * 128);
    __nv_bfloat16* yh = y_hi + ((size_t)b * NTOK + m0) * DIM;
    __nv_bfloat16* yl = y_lo + ((size_t)b * NTOK + m0) * DIM;

    #pragma unroll
    for (int i = t; i < 4096; i += 256) {
        int r = i >> 5, c = (i & 31) * 4;
        float4 v = *(const float4*)(base + (size_t)r * 128 + c);
        if (ns > 1) {
            const float4 w = *(const float4*)(base + 16384 + (size_t)r * 128 + c);
            v.x += w.x; v.y += w.y; v.z += w.z; v.w += w.w;
        }
        if (ns > 2) {
            const float4 w = *(const float4*)(base + 32768 + (size_t)r * 128 + c);
            v.x += w.x; v.y += w.y; v.z += w.z; v.w += w.w;
        }
        float inv = sinv[r];
        split_write2(yh + (size_t)r * DIM + c,     yl + (size_t)r * DIM + c,
                     v.x * inv, v.y * inv);
        split_write2(yh + (size_t)r * DIM + c + 2, yl + (size_t)r * DIM + c + 2,
                     v.z * inv, v.w * inv);
    }
}

// ============================ launch ============================
extern "C" void kernel_launch(void* const* d_in, const int* in_sizes, int n_in,
                              void* d_out, int out_size)
{
    const float* x       = (const float*)d_in[0];
    const float* g_w     = (const float*)d_in[1];
    const float* g_b     = (const float*)d_in[2];
    const float* theta_w = (const float*)d_in[3];
    const float* theta_b = (const float*)d_in[4];
    const float* phi_w   = (const float*)d_in[5];
    const float* phi_b   = (const float*)d_in[6];
    const float* w_w     = (const float*)d_in[7];
    const float* w_b     = (const float*)d_in[8];
    const float* gamma   = (const float*)d_in[9];
    const float* beta    = (const float*)d_in[10];
    float* out = (float*)d_out;

    float *wy, *ps1, *ps2, *py, *prs;
    __nv_bfloat16 *xth, *xtl, *thh, *thl, *phh, *phl, *ghh, *ghl, *y_hi, *y_lo;
    __nv_bfloat16 *wth, *wtl, *wph, *wpl, *wgh, *wgl, *wwh, *wwl;
    cudaGetSymbolAddress((void**)&wy,   g_wy);
    cudaGetSymbolAddress((void**)&ps1,  g_ps1);
    cudaGetSymbolAddress((void**)&ps2,  g_ps2);
    cudaGetSymbolAddress((void**)&py,   g_py);
    cudaGetSymbolAddress((void**)&prs,  g_prs);
    cudaGetSymbolAddress((void**)&xth,  g_xt_hi);
    cudaGetSymbolAddress((void**)&xtl,  g_xt_lo);
    cudaGetSymbolAddress((void**)&thh,  g_th_hi);
    cudaGetSymbolAddress((void**)&thl,  g_th_lo);
    cudaGetSymbolAddress((void**)&phh,  g_ph_hi);
    cudaGetSymbolAddress((void**)&phl,  g_ph_lo);
    cudaGetSymbolAddress((void**)&ghh,  g_g_hi);
    cudaGetSymbolAddress((void**)&ghl,  g_g_lo);
    cudaGetSymbolAddress((void**)&y_hi, g_y_hi);
    cudaGetSymbolAddress((void**)&y_lo, g_y_lo);
    cudaGetSymbolAddress((void**)&wth,  g_wt_hi);
    cudaGetSymbolAddress((void**)&wtl,  g_wt_lo);
    cudaGetSymbolAddress((void**)&wph,  g_wp_hi);
    cudaGetSymbolAddress((void**)&wpl,  g_wp_lo);
    cudaGetSymbolAddress((void**)&wgh,  g_wg_hi);
    cudaGetSymbolAddress((void**)&wgl,  g_wg_lo);
    cudaGetSymbolAddress((void**)&wwh,  g_ww_hi);
    cudaGetSymbolAddress((void**)&wwl,  g_ww_lo);

    cudaFuncSetAttribute(fused_attn, cudaFuncAttributeMaxDynamicSharedMemorySize, FUSED_SMEM);
    cudaFuncSetAttribute(proj3,  cudaFuncAttributeMaxDynamicSharedMemorySize, SMEM_TT);
    cudaFuncSetAttribute(mma_wy, cudaFuncAttributeMaxDynamicSharedMemorySize, SMEM_WY);

    // split inputs (x transpose + weights, single launch)
    split_inputs<<<4096 + 128, 256>>>(x, theta_w, phi_w, g_w, w_w,
                                      xth, xtl, wth, wtl, wph, wpl, wgh, wgl, wwh, wwl);

    // projections (persistent, one launch)
    proj3<<<NCTA, 256, SMEM_TT>>>(
        xth, xtl, wth, wtl, wph, wpl, wgh, wgl,
        thh, thl, phh, phl, ghh, ghl, theta_b, phi_b, g_b);

    // persistent split-K fused attention -> partials
    fused_attn<<<NCTA, 256, FUSED_SMEM>>>(thh, thl, phh, phl, ghh, ghl, py, prs);

    // combine partials -> normalized y (bf16 hi/lo)
    combine_y<<<128, 256>>>(py, prs, y_hi, y_lo);

    // back-projection + BN partial stats
    mma_wy<<<dim3(32, 2, BATCH), 256, SMEM_WY>>>(wwh, wwl, y_hi, y_lo, wy, w_b, ps1, ps2);

    // batchnorm reduce + apply
    bn_reduce<<<CHAN, 128>>>(ps1, ps2);
    bn_apply<<<(BATCH * CHAN * NTOK / 4) / 256, 256>>>(wy, x, gamma, beta, out);
}

// round 15
// speedup vs baseline: 1.0298x; 1.0298x over previous
#include <cuda_runtime.h>
#include <cuda_bf16.h>
#include <cstdint>
#include <math.h>

#define BATCH 4
#define CHAN  256
#define DIM   128
#define NTOK  4096
#define NCTA  148
#define NCHUNK (128 * 64)      // 128 tiles x 64 key-blocks

// ============================ scratch ============================
__device__ __nv_bfloat16 g_xt_hi[BATCH * NTOK * CHAN];
__device__ __nv_bfloat16 g_xt_lo[BATCH * NTOK * CHAN];
__device__ __nv_bfloat16 g_th_hi[BATCH * NTOK * DIM];
__device__ __nv_bfloat16 g_th_lo[BATCH * NTOK * DIM];
__device__ __nv_bfloat16 g_ph_hi[BATCH * NTOK * DIM];
__device__ __nv_bfloat16 g_ph_lo[BATCH * NTOK * DIM];
__device__ __nv_bfloat16 g_g_hi[BATCH * DIM * NTOK];
__device__ __nv_bfloat16 g_g_lo[BATCH * DIM * NTOK];
__device__ __nv_bfloat16 g_y_hi[BATCH * NTOK * DIM];
__device__ __nv_bfloat16 g_y_lo[BATCH * NTOK * DIM];
__device__ __nv_bfloat16 g_wt_hi[DIM * CHAN], g_wt_lo[DIM * CHAN];
__device__ __nv_bfloat16 g_wp_hi[DIM * CHAN], g_wp_lo[DIM * CHAN];
__device__ __nv_bfloat16 g_wg_hi[DIM * CHAN], g_wg_lo[DIM * CHAN];
__device__ __nv_bfloat16 g_ww_hi[CHAN * DIM], g_ww_lo[CHAN * DIM];
__device__ float g_wy[BATCH * CHAN * NTOK];
__device__ float g_ps1[BATCH * 32 * CHAN];
__device__ float g_ps2[BATCH * 32 * CHAN];
__device__ float g_mean[CHAN];
__device__ float g_istd[CHAN];
__device__ float g_py [128 * 3 * 128 * 128];   // partial y   [tile][slot][r][c]
__device__ float g_prs[128 * 3 * 128];         // partial rowsum

// ============================ helpers ============================
__device__ __forceinline__ uint32_t smem_to_u32(const void* p) {
    uint32_t a;
    asm("{ .reg .u64 t; cvta.to.shared.u64 t, %1; cvt.u32.u64 %0, t; }" : "=r"(a) : "l"(p));
    return a;
}
__device__ __forceinline__ void cpa16(uint32_t saddr, const void* g) {
    asm volatile("cp.async.cg.shared.global [%0], [%1], 16;" :: "r"(saddr), "l"(g));
}
__device__ __forceinline__ void cpa_commit() {
    asm volatile("cp.async.commit_group;" ::: "memory");
}
__device__ __forceinline__ void cpa_wait1() {
    asm volatile("cp.async.wait_group 1;" ::: "memory");
}
__device__ __forceinline__ void ldsm_x4(uint32_t* r, uint32_t addr) {
    asm volatile("ldmatrix.sync.aligned.m8n8.x4.shared.b16 {%0,%1,%2,%3}, [%4];"
                 : "=r"(r[0]), "=r"(r[1]), "=r"(r[2]), "=r"(r[3]) : "r"(addr));
}
__device__ __forceinline__ void mma_bf16(float* c, const uint32_t* a, const uint32_t* b) {
    asm volatile("mma.sync.aligned.m16n8k16.row.col.f32.bf16.bf16.f32 "
                 "{%0,%1,%2,%3}, {%4,%5,%6,%7}, {%8,%9}, {%0,%1,%2,%3};"
                 : "+f"(c[0]), "+f"(c[1]), "+f"(c[2]), "+f"(c[3])
                 : "r"(a[0]), "r"(a[1]), "r"(a[2]), "r"(a[3]), "r"(b[0]), "r"(b[1]));
}
__device__ __forceinline__ void split_write2(__nv_bfloat16* hi, __nv_bfloat16* lo,
                                             float a, float b) {
    __nv_bfloat16 h0 = __float2bfloat16_rn(a), h1 = __float2bfloat16_rn(b);
    __nv_bfloat16 l0 = __float2bfloat16_rn(a - __bfloat162float(h0));
    __nv_bfloat16 l1 = __float2bfloat16_rn(b - __bfloat162float(h1));
    *(__nv_bfloat162*)hi = __nv_bfloat162(h0, h1);
    *(__nv_bfloat162*)lo = __nv_bfloat162(l0, l1);
}
__device__ __forceinline__ uint32_t pack_split(float a, float b, uint32_t& lo_out) {
    __nv_bfloat16 ha = __float2bfloat16_rn(a), hb = __float2bfloat16_rn(b);
    __nv_bfloat16 la = __float2bfloat16_rn(a - __bfloat162float(ha));
    __nv_bfloat16 lb = __float2bfloat16_rn(b - __bfloat162float(hb));
    __nv_bfloat162 h(ha, hb), l(la, lb);
    lo_out = *(uint32_t*)&l;
    return *(uint32_t*)&h;
}

// ============================ x transpose + split ============================
__global__ __launch_bounds__(256)
void x_split_T(const float* __restrict__ x,
               __nv_bfloat16* __restrict__ hi, __nv_bfloat16* __restrict__ lo)
{
    __shared__ float tile[32][33];
    const int b = blockIdx.z, c0 = blockIdx.y * 32, n0 = blockIdx.x * 32;
    const int tr = threadIdx.x >> 5, tc = threadIdx.x & 31;
    const float* src = x + ((size_t)b * CHAN + c0) * NTOK + n0;
    #pragma unroll
    for (int i = 0; i < 4; i++)
        tile[tr + 8 * i][tc] = src[(size_t)(tr + 8 * i) * NTOK + tc];
    __syncthreads();
    __nv_bfloat16* ph = hi + ((size_t)b * NTOK + n0) * CHAN + c0;
    __nv_bfloat16* pl = lo + ((size_t)b * NTOK + n0) * CHAN + c0;
    #pragma unroll
    for (int i = 0; i < 4; i++) {
        int rn = tr + 8 * i;
        float v = tile[tc][rn];
        __nv_bfloat16 h = __float2bfloat16_rn(v);
        ph[(size_t)rn * CHAN + tc] = h;
        pl[(size_t)rn * CHAN + tc] = __float2bfloat16_rn(v - __bfloat162float(h));
    }
}

// ============================ weight split ============================
__global__ __launch_bounds__(256)
void weights_split(const float* __restrict__ wt, const float* __restrict__ wp,
                   const float* __restrict__ wg, const float* __restrict__ ww,
                   __nv_bfloat16* __restrict__ th, __nv_bfloat16* __restrict__ tl,
                   __nv_bfloat16* __restrict__ ph, __nv_bfloat16* __restrict__ pl,
                   __nv_bfloat16* __restrict__ gh, __nv_bfloat16* __restrict__ gl,
                   __nv_bfloat16* __restrict__ wh, __nv_bfloat16* __restrict__ wl)
{
    int idx = blockIdx.x * 256 + threadIdx.x;
    const float* srcs[4] = {wt, wp, wg, ww};
    __nv_bfloat16* his[4] = {th, ph, gh, wh};
    __nv_bfloat16* los[4] = {tl, pl, gl, wl};
    #pragma unroll
    for (int s = 0; s < 4; s++) {
        float v = srcs[s][idx];
        __nv_bfloat16 h = __float2bfloat16_rn(v);
        his[s][idx] = h;
        los[s][idx] = __float2bfloat16_rn(v - __bfloat162float(h));
    }
}

// ============================ merged projection GEMM ============================
#define SMEM_TT (2 * (2 * 128 * 80 + 2 * 128 * 80))   // 81920

__global__ __launch_bounds__(256, 2)
void proj3(const __nv_bfloat16* __restrict__ xth, const __nv_bfloat16* __restrict__ xtl,
           const __nv_bfloat16* __restrict__ wth, const __nv_bfloat16* __restrict__ wtl,
           const __nv_bfloat16* __restrict__ wph, const __nv_bfloat16* __restrict__ wpl,
           const __nv_bfloat16* __restrict__ wgh, const __nv_bfloat16* __restrict__ wgl,
           __nv_bfloat16* __restrict__ thh, __nv_bfloat16* __restrict__ thl,
           __nv_bfloat16* __restrict__ phh, __nv_bfloat16* __restrict__ phl,
           __nv_bfloat16* __restrict__ ghh, __nv_bfloat16* __restrict__ ghl,
           const float* __restrict__ tb, const float* __restrict__ pb,
           const float* __restrict__ gb)
{
    constexpr int A_BYTES = 128 * 80;
    constexpr int B_BYTES = 128 * 80;
    constexpr int SS = 2 * A_BYTES + 2 * B_BYTES;

    extern __shared__ char smem[];
    const uint32_t sb = smem_to_u32(smem);

    const int tid = threadIdx.x;
    const int lane = tid & 31, wid = tid >> 5;
    const int wr = wid >> 2, wc = wid & 3;
    const int role = blockIdx.x;
    const int by = blockIdx.y;
    const int b = blockIdx.z;
    const size_t xoff = (size_t)b * NTOK * CHAN + (size_t)by * 128 * CHAN;

    const __nv_bfloat16 *pAh, *pAl, *pBh, *pBl;
    if (role == 0)      { pAh = xth + xoff; pAl = xtl + xoff; pBh = wth; pBl = wtl; }
    else if (role == 1) { pAh = xth + xoff; pAl = xtl + xoff; pBh = wph; pBl = wpl; }
    else                { pAh = wgh;        pAl = wgl;        pBh = xth + xoff; pBl = xtl + xoff; }

    float acc[4][4][4] = {};

    const int a_rl = ((lane >> 3) & 1) * 8 + (lane & 7);
    const int a_cl = lane >> 4;
    const int b_rl = (lane >> 4) * 8 + (lane & 7);
    const int b_cl = (lane >> 3) & 1;

    auto load_stage = [&](int s, int kc) {
        const uint32_t st = sb + s * SS;
        const int k0 = kc * 32;
        #pragma unroll
        for (int i = tid; i < 512; i += 256) {
            int r = i >> 2, c = i & 3;
            uint32_t so = st + r * 80 + c * 16;
            size_t g = (size_t)r * CHAN + k0 + c * 8;
            cpa16(so,           pAh + g);
            cpa16(so + A_BYTES, pAl + g);
        }
        #pragma unroll
        for (int i = tid; i < 512; i += 256) {
            int r = i >> 2, c = i & 3;
            uint32_t so = st + 2 * A_BYTES + r * 80 + c * 16;
            size_t g = (size_t)r * CHAN + k0 + c * 8;
            cpa16(so,           pBh + g);
            cpa16(so + B_BYTES, pBl + g);
        }
    };

    load_stage(0, 0); cpa_commit();
    load_stage(1, 1); cpa_commit();

    for (int kc = 0; kc < 8; kc++) {
        cpa_wait1();
        __syncthreads();
        const uint32_t st = sb + (kc & 1) * SS;
        const uint32_t uAh = st, uAl = st + A_BYTES;
        const uint32_t uBh = st + 2 * A_BYTES, uBl = uBh + B_BYTES;

        #pragma unroll
        for (int ks = 0; ks < 2; ks++) {
            const int kk8 = ks * 2;
            uint32_t bh[4][2], bl[4][2];
            #pragma unroll
            for (int j2 = 0; j2 < 2; j2++) {
                int nrow = wc * 32 + j2 * 16 + b_rl;
                uint32_t off = (uint32_t)(nrow * 80 + (kk8 + b_cl) * 16);
                uint32_t r[4];
                ldsm_x4(r, uBh + off);
                bh[j2 * 2 + 0][0] = r[0]; bh[j2 * 2 + 0][1] = r[1];
                bh[j2 * 2 + 1][0] = r[2]; bh[j2 * 2 + 1][1] = r[3];
                ldsm_x4(r, uBl + off);
                bl[j2 * 2 + 0][0] = r[0]; bl[j2 * 2 + 0][1] = r[1];
                bl[j2 * 2 + 1][0] = r[2]; bl[j2 * 2 + 1][1] = r[3];
            }
            #pragma unroll
            for (int t = 0; t < 4; t++) {
                int mrow = wr * 64 + t * 16 + a_rl;
                uint32_t off = (uint32_t)(mrow * 80 + (kk8 + a_cl) * 16);
                uint32_t ah[4], al[4];
                ldsm_x4(ah, uAh + off);
                ldsm_x4(al, uAl + off);
                #pragma unroll
                for (int j = 0; j < 4; j++) mma_bf16(acc[t][j], ah, bh[j]);
                #pragma unroll
                for (int j = 0; j < 4; j++) mma_bf16(acc[t][j], ah, bl[j]);
                #pragma unroll
                for (int j = 0; j < 4; j++) mma_bf16(acc[t][j], al, bh[j]);
            }
        }
        __syncthreads();
        int nk = kc + 2;
        if (nk < 8) load_stage(kc & 1, nk);
        cpa_commit();
    }

    if (role < 2) {
        const float* bias = role ? pb : tb;
        __nv_bfloat16* oh = (role ? phh : thh) + (size_t)b * NTOK * DIM;
        __nv_bfloat16* ol = (role ? phl : thl) + (size_t)b * NTOK * DIM;
        #pragma unroll
        for (int t = 0; t < 4; t++) {
            int row = by * 128 + wr * 64 + t * 16 + (lane >> 2);
            #pragma unroll
            for (int j = 0; j < 4; j++) {
                int col = wc * 32 + j * 8 + ((lane & 3) << 1);
                float c0 = bias[col], c1 = bias[col + 1];
                split_write2(oh + (size_t)row * DIM + col, ol + (size_t)row * DIM + col,
                             acc[t][j][0] + c0, acc[t][j][1] + c1);
                split_write2(oh + (size_t)(row + 8) * DIM + col, ol + (size_t)(row + 8) * DIM + col,
                             acc[t][j][2] + c0, acc[t][j][3] + c1);
            }
        }
    } else {
        __nv_bfloat16* oh = ghh + (size_t)b * DIM * NTOK;
        __nv_bfloat16* ol = ghl + (size_t)b * DIM * NTOK;
        #pragma unroll
        for (int t = 0; t < 4; t++) {
            int row = wr * 64 + t * 16 + (lane >> 2);
            float r0 = gb[row], r1 = gb[row + 8];
            #pragma unroll
            for (int j = 0; j < 4; j++) {
                int col = by * 128 + wc * 32 + j * 8 + ((lane & 3) << 1);
                split_write2(oh + (size_t)row * NTOK + col, ol + (size_t)row * NTOK + col,
                             acc[t][j][0] + r0, acc[t][j][1] + r0);
                split_write2(oh + (size_t)(row + 8) * NTOK + col, ol + (size_t)(row + 8) * NTOK + col,
                             acc[t][j][2] + r1, acc[t][j][3] + r1);
            }
        }
    }
}

// ============================ wy GEMM + BN partial stats ============================
#define SMEM_WY (SMEM_TT + 4096)

__global__ __launch_bounds__(256, 2)
void mma_wy(const __nv_bfloat16* __restrict__ Ah, const __nv_bfloat16* __restrict__ Al,
            const __nv_bfloat16* __restrict__ Bh, const __nv_bfloat16* __restrict__ Bl,
            float* __restrict__ C, const float* __restrict__ bias,
            float* __restrict__ ps1, float* __restrict__ ps2)
{
    constexpr int A_BYTES = 128 * 80;
    constexpr int B_BYTES = 128 * 80;
    constexpr int SS = 2 * A_BYTES + 2 * B_BYTES;

    extern __shared__ char smem[];
    const uint32_t sb = smem_to_u32(smem);
    float* sred = (float*)(smem + 2 * SS);

    const int tid = threadIdx.x;
    const int lane = tid & 31, wid = tid >> 5;
    const int wr = wid >> 2, wc = wid & 3;
    const int b  = blockIdx.z;
    const int m0 = blockIdx.y * 128;
    const int n0 = blockIdx.x * 128;

    const __nv_bfloat16* pAh = Ah + (size_t)m0 * DIM;
    const __nv_bfloat16* pAl = Al + (size_t)m0 * DIM;
    const __nv_bfloat16* pBh = Bh + (size_t)b * NTOK * DIM + (size_t)n0 * DIM;
    const __nv_bfloat16* pBl = Bl + (size_t)b * NTOK * DIM + (size_t)n0 * DIM;

    float acc[4][4][4] = {};

    const int a_rl = ((lane >> 3) & 1) * 8 + (lane & 7);
    const int a_cl = lane >> 4;
    const int b_rl = (lane >> 4) * 8 + (lane & 7);
    const int b_cl = (lane >> 3) & 1;

    auto load_stage = [&](int s, int kc) {
        const uint32_t st = sb + s * SS;
        const int k0 = kc * 32;
        #pragma unroll
        for (int i = tid; i < 512; i += 256) {
            int r = i >> 2, c = i & 3;
            uint32_t so = st + r * 80 + c * 16;
            size_t g = (size_t)r * DIM + k0 + c * 8;
            cpa16(so,           pAh + g);
            cpa16(so + A_BYTES, pAl + g);
        }
        #pragma unroll
        for (int i = tid; i < 512; i += 256) {
            int r = i >> 2, c = i & 3;
            uint32_t so = st + 2 * A_BYTES + r * 80 + c * 16;
            size_t g = (size_t)r * DIM + k0 + c * 8;
            cpa16(so,           pBh + g);
            cpa16(so + B_BYTES, pBl + g);
        }
    };

    load_stage(0, 0); cpa_commit();
    load_stage(1, 1); cpa_commit();

    for (int kc = 0; kc < 4; kc++) {
        cpa_wait1();
        __syncthreads();
        const uint32_t st = sb + (kc & 1) * SS;
        const uint32_t uAh = st, uAl = st + A_BYTES;
        const uint32_t uBh = st + 2 * A_BYTES, uBl = uBh + B_BYTES;

        #pragma unroll
        for (int ks = 0; ks < 2; ks++) {
            const int kk8 = ks * 2;
            uint32_t bh[4][2], bl[4][2];
            #pragma unroll
            for (int j2 = 0; j2 < 2; j2++) {
                int nrow = wc * 32 + j2 * 16 + b_rl;
                uint32_t off = (uint32_t)(nrow * 80 + (kk8 + b_cl) * 16);
                uint32_t r[4];
                ldsm_x4(r, uBh + off);
                bh[j2 * 2 + 0][0] = r[0]; bh[j2 * 2 + 0][1] = r[1];
                bh[j2 * 2 + 1][0] = r[2]; bh[j2 * 2 + 1][1] = r[3];
                ldsm_x4(r, uBl + off);
                bl[j2 * 2 + 0][0] = r[0]; bl[j2 * 2 + 0][1] = r[1];
                bl[j2 * 2 + 1][0] = r[2]; bl[j2 * 2 + 1][1] = r[3];
            }
            #pragma unroll
            for (int t = 0; t < 4; t++) {
                int mrow = wr * 64 + t * 16 + a_rl;
                uint32_t off = (uint32_t)(mrow * 80 + (kk8 + a_cl) * 16);
                uint32_t ah[4], al[4];
                ldsm_x4(ah, uAh + off);
                ldsm_x4(al, uAl + off);
                #pragma unroll
                for (int j = 0; j < 4; j++) mma_bf16(acc[t][j], ah, bh[j]);
                #pragma unroll
                for (int j = 0; j < 4; j++) mma_bf16(acc[t][j], ah, bl[j]);
                #pragma unroll
                for (int j = 0; j < 4; j++) mma_bf16(acc[t][j], al, bh[j]);
            }
        }
        __syncthreads();
        int nk = kc + 2;
        if (nk < 4) load_stage(kc & 1, nk);
        cpa_commit();
    }

    float s1[8] = {}, s2[8] = {};
    float* Cp = C + (size_t)b * CHAN * NTOK;
    #pragma unroll
    for (int t = 0; t < 4; t++) {
        int row = m0 + wr * 64 + t * 16 + (lane >> 2);
        float b0 = bias[row], b1 = bias[row + 8];
        #pragma unroll
        for (int j = 0; j < 4; j++) {
            int col = n0 + wc * 32 + j * 8 + ((lane & 3) << 1);
            float v0 = acc[t][j][0] + b0, v1 = acc[t][j][1] + b0;
            float v2 = acc[t][j][2] + b1, v3 = acc[t][j][3] + b1;
            *(float2*)(Cp + (size_t)row * NTOK + col)       = make_float2(v0, v1);
            *(float2*)(Cp + (size_t)(row + 8) * NTOK + col) = make_float2(v2, v3);
            s1[t * 2 + 0] += v0 + v1;  s2[t * 2 + 0] += v0 * v0 + v1 * v1;
            s1[t * 2 + 1] += v2 + v3;  s2[t * 2 + 1] += v2 * v2 + v3 * v3;
        }
    }
    #pragma unroll
    for (int i = 0; i < 8; i++) {
        s1[i] += __shfl_xor_sync(0xffffffffu, s1[i], 1);
        s1[i] += __shfl_xor_sync(0xffffffffu, s1[i], 2);
        s2[i] += __shfl_xor_sync(0xffffffffu, s2[i], 1);
        s2[i] += __shfl_xor_sync(0xffffffffu, s2[i], 2);
    }
    __syncthreads();
    if ((lane & 3) == 0) {
        #pragma unroll
        for (int i = 0; i < 8; i++) {
            int rl = (i >> 1) * 16 + (lane >> 2) + (i & 1) * 8;
            sred[(wr * 4 + wc) * 64 + rl] = s1[i];
            sred[512 + (wr * 4 + wc) * 64 + rl] = s2[i];
        }
    }
    __syncthreads();
    if (tid < 128) {
        int wrx = tid >> 6, rl = tid & 63;
        float a1 = 0.0f, a2 = 0.0f;
        #pragma unroll
        for (int w = 0; w < 4; w++) {
            a1 += sred[(wrx * 4 + w) * 64 + rl];
            a2 += sred[512 + (wrx * 4 + w) * 64 + rl];
        }
        int c = m0 + wrx * 64 + rl;
        size_t pidx = ((size_t)b * 32 + blockIdx.x) * CHAN + c;
        ps1[pidx] = a1;
        ps2[pidx] = a2;
    }
}

// ============================ BN reduce ============================
__global__ __launch_bounds__(128)
void bn_reduce(const float* __restrict__ ps1, const float* __restrict__ ps2)
{
    const int c = blockIdx.x;
    const int t = threadIdx.x;
    float s1 = ps1[(size_t)t * CHAN + c];
    float s2 = ps2[(size_t)t * CHAN + c];
    #pragma unroll
    for (int o = 16; o; o >>= 1) {
        s1 += __shfl_xor_sync(0xffffffffu, s1, o);
        s2 += __shfl_xor_sync(0xffffffffu, s2, o);
    }
    __shared__ float r1[4], r2[4];
    if ((t & 31) == 0) { r1[t >> 5] = s1; r2[t >> 5] = s2; }
    __syncthreads();
    if (t == 0) {
        s1 = (r1[0] + r1[1]) + (r1[2] + r1[3]);
        s2 = (r2[0] + r2[1]) + (r2[2] + r2[3]);
        float mean = s1 * (1.0f / 16384.0f);
        float var  = s2 * (1.0f / 16384.0f) - mean * mean;
        g_mean[c] = mean;
        g_istd[c] = rsqrtf(var + 1e-5f);
    }
}

// ============================ BN apply + residual ============================
__global__ __launch_bounds__(256)
void bn_apply(const float* __restrict__ wy, const float* __restrict__ x,
              const float* __restrict__ gamma, const float* __restrict__ beta,
              float* __restrict__ out)
{
    int i4 = blockIdx.x * 256 + threadIdx.x;
    int c = (i4 >> 10) & (CHAN - 1);
    float is = g_istd[c];
    float ga = gamma[c] * is;
    float be = beta[c] - g_mean[c] * ga;
    float4 w = ((const float4*)wy)[i4];
    float4 xx = ((const float4*)x)[i4];
    float4 o;
    o.x = w.x * ga + be + xx.x;
    o.y = w.y * ga + be + xx.y;
    o.z = w.z * ga + be + xx.z;
    o.w = w.w * ga + be + xx.w;
    ((float4*)out)[i4] = o;
}

// ============================ persistent fused attention (split-K) ============================
#define TH_STR   272
#define PHI_STR  272
#define G_STR    144
#define TH_HALF  (128 * TH_STR)
#define TH_BYTES (2 * TH_HALF)
#define PHI_HALF (64 * PHI_STR)
#define PHI_STAGE (2 * PHI_HALF)
#define G_HALF   (128 * G_STR)
#define G_STAGE  (2 * G_HALF)
#define PHI_OFF  TH_BYTES
#define G_OFF    (PHI_OFF + 2 * PHI_STAGE)
#define FUSED_SMEM (G_OFF + 2 * G_STAGE)

__global__ __launch_bounds__(256, 1)
void fused_attn(const __nv_bfloat16* __restrict__ thh, const __nv_bfloat16* __restrict__ thl,
                const __nv_bfloat16* __restrict__ phh, const __nv_bfloat16* __restrict__ phl,
                const __nv_bfloat16* __restrict__ ghh, const __nv_bfloat16* __restrict__ ghl,
                float* __restrict__ py, float* __restrict__ prs)
{
    extern __shared__ char smem[];
    const uint32_t sb = smem_to_u32(smem);
    const int tid = threadIdx.x;
    const int lane = tid & 31, wid = tid >> 5;
    const int k = blockIdx.x;

    const int c0 = (NCHUNK * k) / NCTA;
    const int c1 = (NCHUNK * (k + 1)) / NCTA;

    const int a_rl = ((lane >> 3) & 1) * 8 + (lane & 7);
    const int a_cl = lane >> 4;
    const int b_rl = (lane >> 4) * 8 + (lane & 7);
    const int b_cl = (lane >> 3) & 1;

    int cpos = c0;
    while (cpos < c1) {
        const int tile = cpos >> 6;
        const int tstart = tile << 6;
        const int it0 = cpos - tstart;
        const int it1 = min(c1 - tstart, 64);
        const int b = tile >> 5;
        const int m0 = (tile & 31) * 128;
        const int kfirst = (NCTA * (tstart + 1) - 1) / NCHUNK;
        const int slot = k - kfirst;

        const __nv_bfloat16* pth = thh + ((size_t)b * NTOK + m0) * DIM;
        const __nv_bfloat16* ptl = thl + ((size_t)b * NTOK + m0) * DIM;
        const __nv_bfloat16* pph = phh + (size_t)b * NTOK * DIM;
        const __nv_bfloat16* ppl = phl + (size_t)b * NTOK * DIM;
        const __nv_bfloat16* pgh = ghh + (size_t)b * DIM * NTOK;
        const __nv_bfloat16* pgl = ghl + (size_t)b * DIM * NTOK;

        __syncthreads();   // protect smem reuse across segments

        // theta tile
        #pragma unroll
        for (int i = tid; i < 4096; i += 256) {
            int h = i >> 11, rem = i & 2047;
            int r = rem >> 4, c = rem & 15;
            const __nv_bfloat16* src = h ? ptl : pth;
            cpa16(sb + h * TH_HALF + r * TH_STR + c * 16, src + (size_t)r * DIM + c * 8);
        }

        auto load_stage = [&](int s, int nt) {
            uint32_t pb = sb + PHI_OFF + s * PHI_STAGE;
            const __nv_bfloat16* sph = pph + (size_t)(nt * 64) * DIM;
            const __nv_bfloat16* spl = ppl + (size_t)(nt * 64) * DIM;
            #pragma unroll
            for (int i = tid; i < 2048; i += 256) {
                int h = i >> 10, rem = i & 1023;
                int r = rem >> 4, c = rem & 15;
                const __nv_bfloat16* src = h ? spl : sph;
                cpa16(pb + h * PHI_HALF + r * PHI_STR + c * 16, src + (size_t)r * DIM + c * 8);
            }
            uint32_t gbuf = sb + G_OFF + s * G_STAGE;
            const __nv_bfloat16* sgh = pgh + nt * 64;
            const __nv_bfloat16* sgl = pgl + nt * 64;
            #pragma unroll
            for (int i = tid; i < 2048; i += 256) {
                int h = i >> 10, rem = i & 1023;
                int r = rem >> 3, c = rem & 7;
                const __nv_bfloat16* src = h ? sgl : sgh;
                cpa16(gbuf + h * G_HALF + r * G_STR + c * 16, src + (size_t)r * NTOK + c * 8);
            }
        };

        load_stage(it0 & 1, it0);
        cpa_commit();
        if (it0 + 1 < it1) load_stage((it0 + 1) & 1, it0 + 1);
        cpa_commit();

        float yacc[16][4] = {};
        float rs0 = 0.0f, rs1 = 0.0f;
        const uint32_t a_base = sb + (uint32_t)(16 * wid + a_rl) * TH_STR + a_cl * 16;

        for (int nt = it0; nt < it1; nt++) {
            cpa_wait1();
            __syncthreads();
            const uint32_t uph = sb + PHI_OFF + (nt & 1) * PHI_STAGE;
            const uint32_t ug  = sb + G_OFF + (nt & 1) * G_STAGE;

            float S[8][4] = {};
            #pragma unroll
            for (int ks = 0; ks < 8; ks++) {
                uint32_t ath[4], atl[4];
                uint32_t aoff = a_base + ks * 32;
                ldsm_x4(ath, aoff);
                ldsm_x4(atl, aoff + TH_HALF);
                uint32_t bh[8][2], bl[8][2];
                #pragma unroll
                for (int f = 0; f < 4; f++) {
                    uint32_t boff = (uint32_t)(16 * f + b_rl) * PHI_STR + (2 * ks + b_cl) * 16;
                    uint32_t r[4];
                    ldsm_x4(r, uph + boff);
                    bh[2 * f][0] = r[0]; bh[2 * f][1] = r[1];
                    bh[2 * f + 1][0] = r[2]; bh[2 * f + 1][1] = r[3];
                    ldsm_x4(r, uph + PHI_HALF + boff);
                    bl[2 * f][0] = r[0]; bl[2 * f][1] = r[1];
                    bl[2 * f + 1][0] = r[2]; bl[2 * f + 1][1] = r[3];
                }
                #pragma unroll
                for (int j = 0; j < 8; j++) mma_bf16(S[j], ath, bh[j]);
                #pragma unroll
                for (int j = 0; j < 8; j++) mma_bf16(S[j], ath, bl[j]);
                #pragma unroll
                for (int j = 0; j < 8; j++) mma_bf16(S[j], atl, bh[j]);
            }

            #pragma unroll
            for (int ks2 = 0; ks2 < 4; ks2++) {
                uint32_t gh[16][2], gl[16][2];
                #pragma unroll
                for (int dd = 0; dd < 8; dd++) {
                    uint32_t boff = (uint32_t)(16 * dd + b_rl) * G_STR + (2 * ks2 + b_cl) * 16;
                    uint32_t r[4];
                    ldsm_x4(r, ug + boff);
                    gh[2 * dd][0] = r[0]; gh[2 * dd][1] = r[1];
                    gh[2 * dd + 1][0] = r[2]; gh[2 * dd + 1][1] = r[3];
                    ldsm_x4(r, ug + G_HALF + boff);
                    gl[2 * dd][0] = r[0]; gl[2 * dd][1] = r[1];
                    gl[2 * dd + 1][0] = r[2]; gl[2 * dd + 1][1] = r[3];
                }
                float e0 = __expf(S[2 * ks2][0]),     e1 = __expf(S[2 * ks2][1]);
                float e2 = __expf(S[2 * ks2][2]),     e3 = __expf(S[2 * ks2][3]);
                float e4 = __expf(S[2 * ks2 + 1][0]), e5 = __expf(S[2 * ks2 + 1][1]);
                float e6 = __expf(S[2 * ks2 + 1][2]), e7 = __expf(S[2 * ks2 + 1][3]);
                rs0 += (e0 + e1) + (e4 + e5);
                rs1 += (e2 + e3) + (e6 + e7);
                uint32_t Ph[4], Pl[4];
                Ph[0] = pack_split(e0, e1, Pl[0]);
                Ph[1] = pack_split(e2, e3, Pl[1]);
                Ph[2] = pack_split(e4, e5, Pl[2]);
                Ph[3] = pack_split(e6, e7, Pl[3]);
                #pragma unroll
                for (int j = 0; j < 16; j++) mma_bf16(yacc[j], Ph, gh[j]);
                #pragma unroll
                for (int j = 0; j < 16; j++) mma_bf16(yacc[j], Ph, gl[j]);
                #pragma unroll
                for (int j = 0; j < 16; j++) mma_bf16(yacc[j], Pl, gh[j]);
            }

            __syncthreads();
            if (nt + 2 < it1) load_stage(nt & 1, nt + 2);
            cpa_commit();
        }

        // ---- segment epilogue: partial rowsums + partial fp32 y ----
        rs0 += __shfl_xor_sync(0xffffffffu, rs0, 1);
        rs0 += __shfl_xor_sync(0xffffffffu, rs0, 2);
        rs1 += __shfl_xor_sync(0xffffffffu, rs1, 1);
        rs1 += __shfl_xor_sync(0xffffffffu, rs1, 2);

        float* pys = py + ((size_t)(tile * 3 + slot)) * (128 * 128);
        float* prss = prs + (tile * 3 + slot) * 128;
        int row = 16 * wid + (lane >> 2);
        if ((lane & 3) == 0) { prss[row] = rs0; prss[row + 8] = rs1; }
        #pragma unroll
        for (int j = 0; j < 16; j++) {
            int col = 8 * j + 2 * (lane & 3);
            *(float2*)(pys + (size_t)row * 128 + col)       = make_float2(yacc[j][0], yacc[j][1]);
            *(float2*)(pys + (size_t)(row + 8) * 128 + col) = make_float2(yacc[j][2], yacc[j][3]);
        }

        cpos = tstart + it1;
    }
}

// ============================ combine partials -> normalized split y (coalesced, quarter-tile blocks) ============================
__global__ __launch_bounds__(256)
void combine_y(const float* __restrict__ py, const float* __restrict__ prs,
               __nv_bfloat16* __restrict__ y_hi, __nv_bfloat16* __restrict__ y_lo)
{
    const int tile = blockIdx.x >> 2;         // 0..127
    const int q = blockIdx.x & 3;             // quarter: rows [32q, 32q+32)
    const int b = tile >> 5;
    const int m0 = (tile & 31) * 128;
    const int kfirst = (NCTA * (tile * 64 + 1) - 1) / NCHUNK;
    const int klast  = (NCTA * (tile * 64 + 64) - 1) / NCHUNK;
    const int ns = klast - kfirst + 1;

    const int t = threadIdx.x;
    const int r0 = q * 32;
    __shared__ float sinv[32];
    if (t < 32) {
        float rs = 0.0f;
        for (int s = 0; s < ns; s++) rs += prs[(tile * 3 + s) * 128 + r0 + t];
        sinv[t] = 1.0f / rs;
    }
    __syncthreads();

    const float* base = py + ((size_t)tile * 3) * (128 * 128) + (size_t)r0 * 128;
    __nv_bfloat16* yh = y_hi + ((size_t)b * NTOK + m0 + r0) * DIM;
    __nv_bfloat16* yl = y_lo + ((size_t)b * NTOK + m0 + r0) * DIM;

    // warp-per-row float4 layout over 32 rows: thread i -> (row = i>>5, f4 = i&31)
    #pragma unroll
    for (int i = t; i < 1024; i += 256) {
        int r = i >> 5, c = (i & 31) * 4;
        float4 v = *(const float4*)(base + (size_t)r * 128 + c);
        if (ns > 1) {
            const float4 w = *(const float4*)(base + 16384 + (size_t)r * 128 + c);
            v.x += w.x; v.y += w.y; v.z += w.z; v.w += w.w;
        }
        if (ns > 2) {
            const float4 w = *(const float4*)(base + 32768 + (size_t)r * 128 + c);
            v.x += w.x; v.y += w.y; v.z += w.z; v.w += w.w;
        }
        float inv = sinv[r];
        split_write2(yh + (size_t)r * DIM + c,     yl + (size_t)r * DIM + c,
                     v.x * inv, v.y * inv);
        split_write2(yh + (size_t)r * DIM + c + 2, yl + (size_t)r * DIM + c + 2,
                     v.z * inv, v.w * inv);
    }
}

// ============================ launch ============================
extern "C" void kernel_launch(void* const* d_in, const int* in_sizes, int n_in,
                              void* d_out, int out_size)
{
    const float* x       = (const float*)d_in[0];
    const float* g_w     = (const float*)d_in[1];
    const float* g_b     = (const float*)d_in[2];
    const float* theta_w = (const float*)d_in[3];
    const float* theta_b = (const float*)d_in[4];
    const float* phi_w   = (const float*)d_in[5];
    const float* phi_b   = (const float*)d_in[6];
    const float* w_w     = (const float*)d_in[7];
    const float* w_b     = (const float*)d_in[8];
    const float* gamma   = (const float*)d_in[9];
    const float* beta    = (const float*)d_in[10];
    float* out = (float*)d_out;

    float *wy, *ps1, *ps2, *py, *prs;
    __nv_bfloat16 *xth, *xtl, *thh, *thl, *phh, *phl, *ghh, *ghl, *y_hi, *y_lo;
    __nv_bfloat16 *wth, *wtl, *wph, *wpl, *wgh, *wgl, *wwh, *wwl;
    cudaGetSymbolAddress((void**)&wy,   g_wy);
    cudaGetSymbolAddress((void**)&ps1,  g_ps1);
    cudaGetSymbolAddress((void**)&ps2,  g_ps2);
    cudaGetSymbolAddress((void**)&py,   g_py);
    cudaGetSymbolAddress((void**)&prs,  g_prs);
    cudaGetSymbolAddress((void**)&xth,  g_xt_hi);
    cudaGetSymbolAddress((void**)&xtl,  g_xt_lo);
    cudaGetSymbolAddress((void**)&thh,  g_th_hi);
    cudaGetSymbolAddress((void**)&thl,  g_th_lo);
    cudaGetSymbolAddress((void**)&phh,  g_ph_hi);
    cudaGetSymbolAddress((void**)&phl,  g_ph_lo);
    cudaGetSymbolAddress((void**)&ghh,  g_g_hi);
    cudaGetSymbolAddress((void**)&ghl,  g_g_lo);
    cudaGetSymbolAddress((void**)&y_hi, g_y_hi);
    cudaGetSymbolAddress((void**)&y_lo, g_y_lo);
    cudaGetSymbolAddress((void**)&wth,  g_wt_hi);
    cudaGetSymbolAddress((void**)&wtl,  g_wt_lo);
    cudaGetSymbolAddress((void**)&wph,  g_wp_hi);
    cudaGetSymbolAddress((void**)&wpl,  g_wp_lo);
    cudaGetSymbolAddress((void**)&wgh,  g_wg_hi);
    cudaGetSymbolAddress((void**)&wgl,  g_wg_lo);
    cudaGetSymbolAddress((void**)&wwh,  g_ww_hi);
    cudaGetSymbolAddress((void**)&wwl,  g_ww_lo);

    cudaFuncSetAttribute(fused_attn, cudaFuncAttributeMaxDynamicSharedMemorySize, FUSED_SMEM);
    cudaFuncSetAttribute(proj3,  cudaFuncAttributeMaxDynamicSharedMemorySize, SMEM_TT);
    cudaFuncSetAttribute(mma_wy, cudaFuncAttributeMaxDynamicSharedMemorySize, SMEM_WY);

    // split inputs
    x_split_T<<<dim3(128, 8, BATCH), 256>>>(x, xth, xtl);
    weights_split<<<128, 256>>>(theta_w, phi_w, g_w, w_w,
                                wth, wtl, wph, wpl, wgh, wgl, wwh, wwl);

    // projections (one launch)
    proj3<<<dim3(3, 32, BATCH), 256, SMEM_TT>>>(
        xth, xtl, wth, wtl, wph, wpl, wgh, wgl,
        thh, thl, phh, phl, ghh, ghl, theta_b, phi_b, g_b);

    // persistent split-K fused attention -> partials
    fused_attn<<<NCTA, 256, FUSED_SMEM>>>(thh, thl, phh, phl, ghh, ghl, py, prs);

    // combine partials -> normalized y (bf16 hi/lo), quarter-tile blocks
    combine_y<<<512, 256>>>(py, prs, y_hi, y_lo);

    // back-projection + BN partial stats
    mma_wy<<<dim3(32, 2, BATCH), 256, SMEM_WY>>>(wwh, wwl, y_hi, y_lo, wy, w_b, ps1, ps2);

    // batchnorm reduce + apply
    bn_reduce<<<CHAN, 128>>>(ps1, ps2);
    bn_apply<<<(BATCH * CHAN * NTOK / 4) / 256, 256>>>(wy, x, gamma, beta, out);
}